// round 3
// baseline (speedup 1.0000x reference)
#include <cuda_runtime.h>
#include <cstdint>

#define N_B   32
#define E_DIM 1024
#define IN_DIM 300
#define D_DIM 128
#define NTYPE 3
#define NEG_INF (-9e15f)

// ---------------- persistent device scratch (allowed per rules) ----------------
__device__ float d_vL[NTYPE][N_B][IN_DIM];            // W[t] @ (g*a)_left
__device__ float d_vR[NTYPE][N_B][IN_DIM];            // W[t] @ (g*a)_right
__device__ float d_Lrow[NTYPE][N_B][E_DIM];           // left[t][n][e]
__device__ float d_Rrow[NTYPE][N_B][E_DIM];           // right[t][n][e]
__device__ __align__(16) float d_h2[N_B][E_DIM][D_DIM];           // x @ W[2]  (16 MB)
__device__ __align__(16) unsigned char d_adj8[N_B][E_DIM][E_DIM]; // compressed adj (33.5 MB)
__device__ float d_rmax[N_B][E_DIM];                  // softmax row max
__device__ float d_rinv[N_B][E_DIM];                  // 1 / softmax row sum
__device__ int d_adj_is64;                            // dtype probe result

// ---------------- K0: probe whether adj is int64 or int32 on device ----------------
// int64 with values 0..3 => every odd 32-bit word is 0. int32 random 0..3 =>
// 4096 sampled odd words all-zero with prob 0.25^4096 ~ 0. Deterministic,
// same result every launch, graph-capturable.
__global__ __launch_bounds__(256) void k0_detect(const unsigned int* __restrict__ w)
{
    __shared__ unsigned int r[256];
    unsigned int v = 0;
    for (int i = threadIdx.x; i < 4096; i += 256) v |= w[2 * i + 1];
    r[threadIdx.x] = v;
    __syncthreads();
    for (int s = 128; s; s >>= 1) {
        if (threadIdx.x < s) r[threadIdx.x] |= r[threadIdx.x + s];
        __syncthreads();
    }
    if (threadIdx.x == 0) d_adj_is64 = (r[0] == 0u) ? 1 : 0;
}

// ---------------- K1: gates + projected attention vectors ----------------
// grid (NTYPE, N_B), 256 threads
__global__ __launch_bounds__(256) void k1_gates(
    const float* __restrict__ q, const float* __restrict__ W,
    const float* __restrict__ a, const float* __restrict__ qW1,
    const float* __restrict__ qW2)
{
    int t = blockIdx.x;
    int n = blockIdx.y;
    int tid = threadIdx.x;
    __shared__ float qs[IN_DIM];
    __shared__ float r1[256];
    __shared__ float ga[256];

    for (int k = tid; k < IN_DIM; k += 256) qs[k] = q[n * IN_DIM + k];
    __syncthreads();

    {   // r1 = relu(q @ qW1[t])   (qW1: [3][300][256])
        float acc = 0.f;
        const float* w = qW1 + (size_t)t * IN_DIM * 256 + tid;
        #pragma unroll 4
        for (int k = 0; k < IN_DIM; k++) acc += qs[k] * w[(size_t)k * 256];
        r1[tid] = fmaxf(acc, 0.f);
    }
    __syncthreads();
    {   // g = sigmoid(r1 @ qW2[t]);  ga = g * a[t]
        float acc = 0.f;
        const float* w = qW2 + (size_t)t * 256 * 256 + tid;
        #pragma unroll 4
        for (int k = 0; k < 256; k++) acc += r1[k] * w[(size_t)k * 256];
        float g = 1.f / (1.f + __expf(-acc));
        ga[tid] = g * a[t * 256 + tid];
    }
    __syncthreads();
    // vL[k] = sum_d W[t][k][d]*ga[d];  vR with ga[128+d]
    for (int k = tid; k < IN_DIM; k += 256) {
        const float* w = W + ((size_t)t * IN_DIM + k) * D_DIM;
        float aL = 0.f, aR = 0.f;
        #pragma unroll 4
        for (int dd = 0; dd < D_DIM; dd++) {
            float wv = w[dd];
            aL += wv * ga[dd];
            aR += wv * ga[128 + dd];
        }
        d_vL[t][n][k] = aL;
        d_vR[t][n][k] = aR;
    }
}

// ---------------- K2a: left/right tables, one warp per (n,e) row ----------------
__global__ __launch_bounds__(256) void k2a_leftright(const float* __restrict__ x)
{
    int gw = (blockIdx.x * 256 + threadIdx.x) >> 5;   // 0..32767
    int lane = threadIdx.x & 31;
    int n = gw >> 10;
    int e = gw & 1023;
    const float* row = x + (size_t)(n * E_DIM + e) * IN_DIM;
    float s0 = 0.f, s1 = 0.f, s2 = 0.f, s3 = 0.f, s4 = 0.f, s5 = 0.f;
    for (int k = lane; k < IN_DIM; k += 32) {
        float xv = row[k];
        s0 += xv * d_vL[0][n][k];  s1 += xv * d_vR[0][n][k];
        s2 += xv * d_vL[1][n][k];  s3 += xv * d_vR[1][n][k];
        s4 += xv * d_vL[2][n][k];  s5 += xv * d_vR[2][n][k];
    }
    #pragma unroll
    for (int o = 16; o; o >>= 1) {
        s0 += __shfl_xor_sync(0xffffffffu, s0, o);
        s1 += __shfl_xor_sync(0xffffffffu, s1, o);
        s2 += __shfl_xor_sync(0xffffffffu, s2, o);
        s3 += __shfl_xor_sync(0xffffffffu, s3, o);
        s4 += __shfl_xor_sync(0xffffffffu, s4, o);
        s5 += __shfl_xor_sync(0xffffffffu, s5, o);
    }
    if (lane == 0) {
        d_Lrow[0][n][e] = s0;  d_Rrow[0][n][e] = s1;
        d_Lrow[1][n][e] = s2;  d_Rrow[1][n][e] = s3;
        d_Lrow[2][n][e] = s4;  d_Rrow[2][n][e] = s5;
    }
}

// ---------------- K2b: h2 = x @ W[2]  (128x128 tile, K=300, f32x2 FMA) ----------------
#define BK2 20
__global__ __launch_bounds__(256) void k2b_h2(
    const float* __restrict__ x, const float* __restrict__ W)
{
    int n = blockIdx.y;
    int e0 = blockIdx.x * 128;
    const float* W2 = W + (size_t)2 * IN_DIM * D_DIM;
    int tid = threadIdx.x;
    int tx = tid & 15, ty = tid >> 4;

    __shared__ float As[BK2][132];   // As[k][e]
    __shared__ float Bs[BK2][132];   // Bs[k][d]

    unsigned long long acc[8][4];
    #pragma unroll
    for (int j = 0; j < 8; j++)
        #pragma unroll
        for (int p = 0; p < 4; p++) acc[j][p] = 0ull;

    for (int k0 = 0; k0 < IN_DIM; k0 += BK2) {
        for (int idx = tid; idx < 128 * BK2; idx += 256) {
            int e = idx / BK2, k = idx - e * BK2;
            As[k][e] = x[(size_t)(n * E_DIM + e0 + e) * IN_DIM + k0 + k];
        }
        for (int idx = tid; idx < BK2 * D_DIM; idx += 256) {
            int k = idx >> 7, dd = idx & 127;
            Bs[k][dd] = W2[(size_t)(k0 + k) * D_DIM + dd];
        }
        __syncthreads();
        #pragma unroll 5
        for (int k = 0; k < BK2; k++) {
            unsigned long long bf[4];
            const unsigned long long* bp =
                reinterpret_cast<const unsigned long long*>(&Bs[k][tx * 8]);
            #pragma unroll
            for (int p = 0; p < 4; p++) bf[p] = bp[p];
            float af[8];
            #pragma unroll
            for (int j = 0; j < 8; j++) af[j] = As[k][ty * 8 + j];
            #pragma unroll
            for (int j = 0; j < 8; j++) {
                unsigned long long pp;
                unsigned int au = __float_as_uint(af[j]);
                asm("mov.b64 %0, {%1, %1};" : "=l"(pp) : "r"(au));
                #pragma unroll
                for (int p = 0; p < 4; p++)
                    asm("fma.rn.f32x2 %0, %1, %2, %0;"
                        : "+l"(acc[j][p]) : "l"(pp), "l"(bf[p]));
            }
        }
        __syncthreads();
    }
    #pragma unroll
    for (int j = 0; j < 8; j++) {
        float* dst = &d_h2[n][e0 + ty * 8 + j][tx * 8];
        #pragma unroll
        for (int p = 0; p < 4; p++) {
            unsigned int lo, hi;
            asm("mov.b64 {%0, %1}, %2;" : "=r"(lo), "=r"(hi) : "l"(acc[j][p]));
            float2 v = make_float2(__uint_as_float(lo), __uint_as_float(hi));
            *reinterpret_cast<float2*>(dst + 2 * p) = v;
        }
    }
}

// ---------------- K3: softmax row stats + adj -> int8 ----------------
// grid (64, N_B): 16 rows per block, 256 threads. Handles int32 or int64 adj.
__global__ __launch_bounds__(256) void k3_stats(const void* __restrict__ adjv)
{
    int n = blockIdx.y;
    int i0 = blockIdx.x * 16;
    int tid = threadIdx.x;
    int lane = tid & 31, wid = tid >> 5;
    int is64 = d_adj_is64;

    __shared__ float Rs[NTYPE][E_DIM];   // 12 KB
    __shared__ float redm[8];
    __shared__ float reds[8];

    for (int idx = tid; idx < NTYPE * E_DIM; idx += 256) {
        int t = idx >> 10, j = idx & 1023;
        Rs[t][j] = d_Rrow[t][n][j];
    }
    __syncthreads();

    for (int r = 0; r < 16; r++) {
        int i = i0 + r;
        float L0 = d_Lrow[0][n][i], L1 = d_Lrow[1][n][i], L2 = d_Lrow[2][n][i];
        size_t rowoff = ((size_t)(n * E_DIM + i)) << 10;
        const int* arow32 = (const int*)adjv + rowoff;
        const long long* arow64 = (const long long*)adjv + rowoff;
        unsigned char* a8row = &d_adj8[n][i][0];

        float s[4];
        float mx = NEG_INF;
        #pragma unroll
        for (int m = 0; m < 4; m++) {
            int j = tid + 256 * m;
            int a = is64 ? (int)arow64[j] : arow32[j];
            float Lt = (a == 1) ? L0 : ((a == 2) ? L1 : L2);
            float sv;
            if (a > 0) {
                float v = Lt + Rs[a - 1][j];
                sv = fmaxf(v, 0.2f * v);       // leaky relu
            } else sv = NEG_INF;
            s[m] = sv;
            mx = fmaxf(mx, sv);
            a8row[j] = (unsigned char)a;
        }
        // block max
        #pragma unroll
        for (int o = 16; o; o >>= 1) mx = fmaxf(mx, __shfl_xor_sync(0xffffffffu, mx, o));
        if (lane == 0) redm[wid] = mx;
        __syncthreads();
        if (tid == 0) {
            float v = redm[0];
            #pragma unroll
            for (int q = 1; q < 8; q++) v = fmaxf(v, redm[q]);
            redm[0] = v;
        }
        __syncthreads();
        float rowmax = redm[0];
        // block sum of exp
        float sum = 0.f;
        #pragma unroll
        for (int m = 0; m < 4; m++) sum += __expf(s[m] - rowmax);
        #pragma unroll
        for (int o = 16; o; o >>= 1) sum += __shfl_xor_sync(0xffffffffu, sum, o);
        if (lane == 0) reds[wid] = sum;
        __syncthreads();
        if (tid == 0) {
            float v = 0.f;
            #pragma unroll
            for (int q = 0; q < 8; q++) v += reds[q];
            d_rmax[n][i] = rowmax;
            d_rinv[n][i] = 1.f / v;
        }
        __syncthreads();
    }
}

// ---------------- K4: out[n] = P^T @ h2[n], P recomputed from adj8 ----------------
// grid (8, N_B): 128 j-cols x 128 d per block, K over i = 0..1023
__global__ __launch_bounds__(256) void k4_pv(float* __restrict__ out)
{
    int n = blockIdx.y;
    int j0 = blockIdx.x * 128;
    int tid = threadIdx.x;
    int tx = tid & 15, ty = tid >> 4;

    __shared__ float Ps[32][132];            // P[i][jj]
    __shared__ float Hs[32][132];            // h2[i][dd]
    __shared__ unsigned char Ad[32][128];
    __shared__ float RsJ[NTYPE][128];
    __shared__ float Lc[NTYPE][32];
    __shared__ float Mc[32], Vc[32];

    for (int idx = tid; idx < NTYPE * 128; idx += 256) {
        int t = idx >> 7, jj = idx & 127;
        RsJ[t][jj] = d_Rrow[t][n][j0 + jj];
    }

    unsigned long long acc[8][4];
    #pragma unroll
    for (int j = 0; j < 8; j++)
        #pragma unroll
        for (int p = 0; p < 4; p++) acc[j][p] = 0ull;

    for (int i0 = 0; i0 < E_DIM; i0 += 32) {
        __syncthreads();   // protect smem from previous iteration's readers
        {
            int ii = tid >> 3;
            int c0 = (tid & 7) * 16;
            *reinterpret_cast<int4*>(&Ad[ii][c0]) =
                *reinterpret_cast<const int4*>(&d_adj8[n][i0 + ii][j0 + c0]);
            const float4* src = reinterpret_cast<const float4*>(&d_h2[n][i0 + ii][c0]);
            float4* dst = reinterpret_cast<float4*>(&Hs[ii][c0]);
            #pragma unroll
            for (int p = 0; p < 4; p++) dst[p] = src[p];
        }
        if (tid < 32) {
            Lc[0][tid] = d_Lrow[0][n][i0 + tid];
            Lc[1][tid] = d_Lrow[1][n][i0 + tid];
            Lc[2][tid] = d_Lrow[2][n][i0 + tid];
            Mc[tid] = d_rmax[n][i0 + tid];
            Vc[tid] = d_rinv[n][i0 + tid];
        }
        __syncthreads();
        {   // compute probabilities tile
            int ii = tid >> 3;
            int c0 = (tid & 7) * 16;
            float m = Mc[ii], inv = Vc[ii];
            float L0 = Lc[0][ii], L1 = Lc[1][ii], L2 = Lc[2][ii];
            #pragma unroll
            for (int c = 0; c < 16; c++) {
                int jj = c0 + c;
                int a = Ad[ii][jj];
                float Lt = (a == 1) ? L0 : ((a == 2) ? L1 : L2);
                float sv;
                if (a > 0) {
                    float v = Lt + RsJ[a - 1][jj];
                    sv = fmaxf(v, 0.2f * v);
                } else sv = NEG_INF;
                Ps[ii][jj] = __expf(sv - m) * inv;
            }
        }
        __syncthreads();
        #pragma unroll 8
        for (int k = 0; k < 32; k++) {
            unsigned long long bf[4];
            const unsigned long long* bp =
                reinterpret_cast<const unsigned long long*>(&Hs[k][tx * 8]);
            #pragma unroll
            for (int p = 0; p < 4; p++) bf[p] = bp[p];
            float af[8];
            #pragma unroll
            for (int j = 0; j < 8; j++) af[j] = Ps[k][ty * 8 + j];
            #pragma unroll
            for (int j = 0; j < 8; j++) {
                unsigned long long pp;
                unsigned int au = __float_as_uint(af[j]);
                asm("mov.b64 %0, {%1, %1};" : "=l"(pp) : "r"(au));
                #pragma unroll
                for (int p = 0; p < 4; p++)
                    asm("fma.rn.f32x2 %0, %1, %2, %0;"
                        : "+l"(acc[j][p]) : "l"(pp), "l"(bf[p]));
            }
        }
    }
    // epilogue: out[n][j0+ty*8+j][tx*8 + ...]
    size_t base = ((size_t)n * E_DIM + j0 + ty * 8) * D_DIM + tx * 8;
    #pragma unroll
    for (int j = 0; j < 8; j++) {
        float* dst = out + base + (size_t)j * D_DIM;
        #pragma unroll
        for (int p = 0; p < 4; p++) {
            unsigned int lo, hi;
            asm("mov.b64 {%0, %1}, %2;" : "=r"(lo), "=r"(hi) : "l"(acc[j][p]));
            float2 v = make_float2(__uint_as_float(lo), __uint_as_float(hi));
            *reinterpret_cast<float2*>(dst + 2 * p) = v;
        }
    }
}

// ---------------- launch ----------------
extern "C" void kernel_launch(void* const* d_in, const int* in_sizes, int n_in,
                              void* d_out, int out_size)
{
    const float*  input_state = (const float*)d_in[0];
    const void*   adj         = (const void*)d_in[1];
    // d_in[2] = entity_mask (unused by reference)
    const float*  query_vec   = (const float*)d_in[3];
    const float*  W           = (const float*)d_in[4];
    const float*  a           = (const float*)d_in[5];
    const float*  qW1         = (const float*)d_in[6];
    const float*  qW2         = (const float*)d_in[7];
    float* out = (float*)d_out;
    (void)in_sizes; (void)n_in; (void)out_size;

    k0_detect<<<1, 256>>>((const unsigned int*)adj);
    k1_gates<<<dim3(NTYPE, N_B), 256>>>(query_vec, W, a, qW1, qW2);
    k2a_leftright<<<(N_B * E_DIM) / 8, 256>>>(input_state);
    k2b_h2<<<dim3(8, N_B), 256>>>(input_state, W);
    k3_stats<<<dim3(64, N_B), 256>>>(adj);
    k4_pv<<<dim3(8, N_B), 256>>>(out);
}